// round 5
// baseline (speedup 1.0000x reference)
#include <cuda_runtime.h>
#include <cuda_bf16.h>
#include <math.h>

// Problem constants (fixed by setup_inputs)
#define BB 16
#define NN 8400
#define CC 80
#define MM 64
#define RR 16
#define KTOP 13
#define NEG_INFF (-1e30f)

static constexpr int T1    = 128;                     // anchors per main block
static constexpr int NB1   = (NN + T1 - 1) / T1;      // 66
static constexpr int NBTOT = NB1 * BB;                // 1056
static constexpr int CAP   = 512;                     // max candidates per GT (<=395 actual)

// ---------------- scratch (static device globals; no allocations) ----------
__device__ unsigned long long g_thr[BB * MM];
__device__ float              g_p2[BB * NB1 * 8];
__device__ unsigned int       g_done = 0;             // reset by last block each run

// ---------------- bit-exact helpers shared by K_A and K_B --------------------
// No FMA contraction allowed here: K_A and K_B must produce identical bits.
__device__ __forceinline__ float iou_sel(float4 a, float4 b) {
    float x1 = fmaxf(a.x, b.x), y1 = fmaxf(a.y, b.y);
    float x2 = fminf(a.z, b.z), y2 = fminf(a.w, b.w);
    float iw = fmaxf(__fsub_rn(x2, x1), 0.f);
    float ih = fmaxf(__fsub_rn(y2, y1), 0.f);
    float inter = __fmul_rn(iw, ih);
    float a1 = __fmul_rn(__fsub_rn(a.z, a.x), __fsub_rn(a.w, a.y));
    float a2 = __fmul_rn(__fsub_rn(b.z, b.x), __fsub_rn(b.w, b.y));
    float den = __fadd_rn(__fsub_rn(__fadd_rn(a1, a2), inter), 1e-7f);
    return __fdiv_rn(inter, den);
}

__device__ __forceinline__ float sigmoid_sel(float x) {   // accurate; selection path
    return __fdiv_rn(1.f, __fadd_rn(1.f, expf(-x)));
}

__device__ __forceinline__ float align_sel(float cls, float iou) {
    float i2 = __fmul_rn(iou, iou);
    float i4 = __fmul_rn(i2, i2);
    float i6 = __fmul_rn(i4, i2);
    return __fmul_rn(cls, i6);                              // alpha=1, beta=6
}

// Sortable key matching jax.lax.top_k semantics: value desc, index asc on ties.
__device__ __forceinline__ unsigned long long pack_key(float v, int n) {
    unsigned int u = __float_as_uint(v);
    u = (u & 0x80000000u) ? ~u : (u | 0x80000000u);
    return ((unsigned long long)u << 32) | (unsigned int)(0xFFFFFFFFu - (unsigned int)n);
}

// class_mask may arrive as uint8 or widened (int32/float32) bools.
// uint8 ones -> bytes 01 01 01 01 (cm[1]!=0); int32/float32 ones -> cm[1]==0.
__device__ __forceinline__ bool mask_at(const unsigned char* cm, bool wide, int idx) {
    return wide ? (((const unsigned int*)cm)[idx] != 0u) : (cm[idx] != 0);
}

// ---------------- K_A: per (b,m) candidate scan -> 13th-largest key ----------
__global__ void __launch_bounds__(256)
k_thr(const float* __restrict__ ps, const float* __restrict__ pb,
      const float* __restrict__ ap, const int* __restrict__ gtl,
      const float* __restrict__ gtb, const unsigned char* __restrict__ cm) {
    const int m = blockIdx.x, b = blockIdx.y;
    const int tid = threadIdx.x;

    __shared__ float4 sbox;
    __shared__ int    slc, svalid, scnt;
    __shared__ unsigned long long skeys[CAP];
    __shared__ unsigned long long sthr;

    if (tid == 0) {
        const float* g = gtb + (b * MM + m) * 4;
        sbox = make_float4(g[0], g[1], g[2], g[3]);
        int l  = gtl[b * MM + m];
        int lc = min(max(l, 0), CC - 1);
        slc = lc;
        const bool wide = (cm[1] == 0);
        svalid = (l >= 0 && l < CC && mask_at(cm, wide, b * CC + lc)) ? 1 : 0;
        scnt = 0;
        sthr = 0ull;
    }
    __syncthreads();

    if (svalid) {
        const float4 box = sbox;
        const int lc = slc;
        for (int n = tid; n < NN; n += 256) {
            float2 a = __ldg((const float2*)ap + n);
            if (a.x >= box.x && a.x <= box.z && a.y >= box.y && a.y <= box.w) {
                float4 pbox = __ldg((const float4*)(pb + ((size_t)b * NN + n) * 4));
                float cls = sigmoid_sel(__ldg(ps + ((size_t)b * NN + n) * CC + lc));
                float al  = align_sel(cls, iou_sel(pbox, box));
                int slot = atomicAdd(&scnt, 1);
                if (slot < CAP) skeys[slot] = pack_key(al, n);
            }
        }
    }
    __syncthreads();

    const int c = min(scnt, CAP);
    if (c >= KTOP) {
        // rank selection: the key with exactly KTOP-1 larger keys is the threshold
        for (int i = tid; i < c; i += 256) {
            unsigned long long k = skeys[i];
            int r = 0;
            for (int j = 0; j < c; j++) r += (skeys[j] > k);
            if (r == KTOP - 1) sthr = k;   // unique (keys distinct by index)
        }
    }
    __syncthreads();
    if (tid == 0) g_thr[b * MM + m] = sthr;
}

// ---------------- K_B: fused per-anchor assignment + loss + finalize ---------
__global__ void __launch_bounds__(T1)
k_main(const float* __restrict__ ps, const float* __restrict__ pb,
       const float* __restrict__ ap, const float* __restrict__ st,
       const int* __restrict__ gtl, const float* __restrict__ gtb,
       const float* __restrict__ bd, const unsigned char* __restrict__ cm,
       float* __restrict__ out) {
    const int b    = blockIdx.y;
    const int tile = blockIdx.x * T1;
    const int tid  = threadIdx.x;
    const int warp = tid >> 5, lane = tid & 31;
    const bool wide = (cm[1] == 0);

    __shared__ float  sps[T1 * 81];     // pitch 81 -> conflict-free column reads
    __shared__ float4 sgtb[MM];
    __shared__ int    slab[MM];
    __shared__ unsigned char svalm[MM];
    __shared__ unsigned long long sthr[MM];
    __shared__ float  svc[CC];
    __shared__ float  spart[4 * 8];
    __shared__ float  sbb[4 * 4];       // per-warp minx,maxx,miny,maxy
    __shared__ int    s_mlist[MM];
    __shared__ int    s_mcnt;
    __shared__ unsigned int s_last;

    if (tid < MM) {
        const float* g = gtb + (b * MM + tid) * 4;
        sgtb[tid] = make_float4(g[0], g[1], g[2], g[3]);
        int l  = gtl[b * MM + tid];
        int lc = min(max(l, 0), CC - 1);
        slab[tid] = lc;
        svalm[tid] = (l >= 0 && l < CC && mask_at(cm, wide, b * CC + lc)) ? 1 : 0;
        sthr[tid] = g_thr[b * MM + tid];
    }
    if (tid < CC) svc[tid] = mask_at(cm, wide, b * CC + tid) ? 1.f : 0.f;

    const int rows = min(T1, NN - tile);
    const int n = tile + tid;
    float ax = 0.f, ay = 0.f;
    float4 pbox = make_float4(0.f, 0.f, 0.f, 0.f);
    if (tid < rows) {
        float2 a = __ldg((const float2*)ap + n);
        ax = a.x; ay = a.y;
        pbox = __ldg((const float4*)(pb + ((size_t)b * NN + n) * 4));
    }

    // ---- tile anchor bbox (for GT pruning) ----------------------------------
    {
        float mnx = (tid < rows) ? ax :  3.4e38f;
        float mxx = (tid < rows) ? ax : -3.4e38f;
        float mny = (tid < rows) ? ay :  3.4e38f;
        float mxy = (tid < rows) ? ay : -3.4e38f;
#pragma unroll
        for (int off = 16; off > 0; off >>= 1) {
            mnx = fminf(mnx, __shfl_down_sync(0xFFFFFFFFu, mnx, off));
            mxx = fmaxf(mxx, __shfl_down_sync(0xFFFFFFFFu, mxx, off));
            mny = fminf(mny, __shfl_down_sync(0xFFFFFFFFu, mny, off));
            mxy = fmaxf(mxy, __shfl_down_sync(0xFFFFFFFFu, mxy, off));
        }
        if (lane == 0) {
            sbb[warp * 4 + 0] = mnx; sbb[warp * 4 + 1] = mxx;
            sbb[warp * 4 + 2] = mny; sbb[warp * 4 + 3] = mxy;
        }
    }
    __syncthreads();

    if (tid == 0) {
        float mnx = fminf(fminf(sbb[0], sbb[4]),  fminf(sbb[8],  sbb[12]));
        float mxx = fmaxf(fmaxf(sbb[1], sbb[5]),  fmaxf(sbb[9],  sbb[13]));
        float mny = fminf(fminf(sbb[2], sbb[6]),  fminf(sbb[10], sbb[14]));
        float mxy = fmaxf(fmaxf(sbb[3], sbb[7]),  fmaxf(sbb[11], sbb[15]));
        int c = 0;
        for (int m = 0; m < MM; m++) {
            float4 g = sgtb[m];
            if (svalm[m] && g.x <= mxx && g.z >= mnx && g.y <= mxy && g.w >= mny)
                s_mlist[c++] = m;        // ascending m -> first-m argmax preserved
        }
        s_mcnt = c;
    }

    // cooperative, coalesced load of ps tile (rows x 80 floats)
    for (int idx = tid; idx < rows * 20; idx += T1) {
        int r = idx / 20, c4 = idx % 20;
        float4 v = __ldg((const float4*)(ps + ((size_t)b * NN + tile + r) * CC) + c4);
        float* dst = &sps[r * 81 + c4 * 4];
        dst[0] = v.x; dst[1] = v.y; dst[2] = v.z; dst[3] = v.w;
    }
    __syncthreads();

    float cnt = 0.f, cis = 0.f, dfs = 0.f, cor = 0.f, pos = 0.f, neg = 0.f, mio = 0.f, sp = 0.f;

    if (tid < rows) {
        const float* myrow = &sps[tid * 81];

        // ---- softplus sum + valid-class max (value-only: fast intrinsics) ----
        float mxl = -3.4e38f; int anyv = 0;
        for (int c = 0; c < CC; c++) {
            float s = myrow[c];
            if (svc[c] != 0.f) {
                sp += fmaxf(s, 0.f) + __logf(1.f + __expf(-fabsf(s)));
                mxl = fmaxf(mxl, s);
                anyv = 1;
            }
        }

        // ---- assignment over pruned GT list ---------------------------------
        float best = -3.4e38f; int mg = 0;
        const int mc = s_mcnt;
        for (int mi = 0; mi < mc; mi++) {
            const int m = s_mlist[mi];
            float4 g = sgtb[m];
            float cand = NEG_INFF;
            if (ax >= g.x && ax <= g.z && ay >= g.y && ay <= g.w) {
                float cls = sigmoid_sel(myrow[slab[m]]);
                float al  = align_sel(cls, iou_sel(pbox, g));
                cand = (pack_key(al, n) >= sthr[m]) ? al : NEG_INFF;
            }
            if (cand > best) { best = cand; mg = m; }   // strict > = first-m argmax
        }
        const bool fg = best > -1.0f;

        if (fg) {
            cnt = 1.f;
            const float4 g = sgtb[mg];
            const int ml = slab[mg];
            const float ov = iou_sel(pbox, g);
            mio = ov;
            float psv = myrow[ml];
            pos = 1.f / (1.f + __expf(-psv));
            cor = psv * fmaxf(ov, 0.1f) * svc[ml];

            // CIoU (value-only accuracy)
            float w1 = pbox.z - pbox.x, h1 = pbox.w - pbox.y;
            float w2 = g.z - g.x,       h2 = g.w - g.y;
            float cw = fmaxf(pbox.z, g.z) - fminf(pbox.x, g.x);
            float ch = fmaxf(pbox.w, g.w) - fminf(pbox.y, g.y);
            float c2 = cw * cw + ch * ch + 1e-7f;
            float dx = g.x + g.z - pbox.x - pbox.z;
            float dy = g.y + g.w - pbox.y - pbox.w;
            float rho2 = (dx * dx + dy * dy) * 0.25f;
            float dat = atanf(w2 / (h2 + 1e-7f)) - atanf(w1 / (h1 + 1e-7f));
            float v   = 0.40528473456935108577f * dat * dat;  // 4/pi^2
            float alp = v / (v - ov + 1.0f + 1e-7f);
            cis = 1.f - (ov - (rho2 / c2 + v * alp));

            // DFL
            const float stv = __ldg(st + n);
            float dar[4] = { (ax - g.x) / stv, (ay - g.y) / stv,
                             (g.z - ax) / stv, (g.w - ay) / stv };
            const float* bdp = bd + ((size_t)b * NN + n) * 64;
            const float4* bq = (const float4*)bdp;
#pragma unroll
            for (int sd = 0; sd < 4; sd++) {
                float4 q0 = __ldg(bq + sd * 4 + 0);
                float4 q1 = __ldg(bq + sd * 4 + 1);
                float4 q2 = __ldg(bq + sd * 4 + 2);
                float4 q3 = __ldg(bq + sd * 4 + 3);
                float mv = q0.x;
                mv = fmaxf(mv, q0.y); mv = fmaxf(mv, q0.z); mv = fmaxf(mv, q0.w);
                mv = fmaxf(mv, q1.x); mv = fmaxf(mv, q1.y); mv = fmaxf(mv, q1.z); mv = fmaxf(mv, q1.w);
                mv = fmaxf(mv, q2.x); mv = fmaxf(mv, q2.y); mv = fmaxf(mv, q2.z); mv = fmaxf(mv, q2.w);
                mv = fmaxf(mv, q3.x); mv = fmaxf(mv, q3.y); mv = fmaxf(mv, q3.z); mv = fmaxf(mv, q3.w);
                float se = __expf(q0.x - mv) + __expf(q0.y - mv) + __expf(q0.z - mv) + __expf(q0.w - mv)
                         + __expf(q1.x - mv) + __expf(q1.y - mv) + __expf(q1.z - mv) + __expf(q1.w - mv)
                         + __expf(q2.x - mv) + __expf(q2.y - mv) + __expf(q2.z - mv) + __expf(q2.w - mv)
                         + __expf(q3.x - mv) + __expf(q3.y - mv) + __expf(q3.z - mv) + __expf(q3.w - mv);
                float lse = mv + __logf(se);
                float d = fminf(fmaxf(dar[sd], 0.f), 14.99f);
                int tl = (int)d;
                int tr = min(tl + 1, RR - 1);
                float wl = (float)tr - d;
                float wr = 1.f - wl;
                float vtl = __ldg(bdp + sd * 16 + tl);
                float vtr = __ldg(bdp + sd * 16 + tr);
                dfs += (lse - vtl) * wl + (lse - vtr) * wr;
            }
        } else {
            neg = anyv ? (1.f / (1.f + __expf(-mxl))) : NEG_INFF;
        }
    }

    // ---- 8-way block reduction (warp shuffles + one smem stage) -------------
    float v[8] = {cnt, cis, dfs, cor, pos, neg, mio, sp};
#pragma unroll
    for (int k = 0; k < 8; k++) {
#pragma unroll
        for (int off = 16; off > 0; off >>= 1)
            v[k] += __shfl_down_sync(0xFFFFFFFFu, v[k], off);
    }
    if (lane == 0) {
#pragma unroll
        for (int k = 0; k < 8; k++) spart[warp * 8 + k] = v[k];
    }
    __syncthreads();
    if (tid == 0) {
        float* o = &g_p2[((size_t)b * NB1 + blockIdx.x) * 8];
#pragma unroll
        for (int k = 0; k < 8; k++)
            o[k] = spart[k] + spart[8 + k] + spart[16 + k] + spart[24 + k];
        __threadfence();
        unsigned int d = atomicAdd(&g_done, 1u);
        s_last = (d == NBTOT - 1) ? 1u : 0u;
    }
    __syncthreads();

    // ---- last block: finalize ----------------------------------------------
    if (s_last) {
        __shared__ float s_match[BB], s_iou[BB], s_dfl[BB], s_cnt[BB], s_pos[BB], s_neg[BB], s_mio[BB];
        // 4 warps, each handles 4 batch samples
        for (int bsel = warp; bsel < BB; bsel += 4) {
            float w[8] = {0.f, 0.f, 0.f, 0.f, 0.f, 0.f, 0.f, 0.f};
            for (int i = lane; i < NB1; i += 32) {
                const float* p = &g_p2[((size_t)bsel * NB1 + i) * 8];
#pragma unroll
                for (int k = 0; k < 8; k++) w[k] += p[k];
            }
            float vcs = 0.f;
            for (int c = lane; c < CC; c += 32)
                vcs += mask_at(cm, wide, bsel * CC + c) ? 1.f : 0.f;
#pragma unroll
            for (int off = 16; off > 0; off >>= 1) {
#pragma unroll
                for (int k = 0; k < 8; k++) w[k] += __shfl_down_sync(0xFFFFFFFFu, w[k], off);
                vcs += __shfl_down_sync(0xFFFFFFFFu, vcs, off);
            }
            if (lane == 0) {
                float cb = w[0];
                s_match[bsel] = (w[7] - w[3]) / ((float)NN * fmaxf(vcs, 1.f));
                s_iou[bsel]   = (cb > 0.f) ? w[1] / fmaxf(cb, 1.f) : 0.f;
                s_dfl[bsel]   = (cb > 0.f) ? w[2] / fmaxf(cb * 4.f, 1.f) : 0.f;
                s_cnt[bsel] = cb; s_pos[bsel] = w[4]; s_neg[bsel] = w[5]; s_mio[bsel] = w[6];
            }
        }
        __syncthreads();
        if (tid == 0) {
            float tm = 0.f, ti = 0.f, td = 0.f, tc = 0.f, tp = 0.f, tn = 0.f, tmi = 0.f;
            for (int i = 0; i < BB; i++) {
                tm += s_match[i]; ti += s_iou[i]; td += s_dfl[i];
                tc += s_cnt[i];  tp += s_pos[i]; tn += s_neg[i]; tmi += s_mio[i];
            }
            float tot_neg = (float)BB * (float)NN - tc;
            out[0] = (0.5f * tm + 7.5f * ti + 1.5f * td) / (float)BB;
            out[1] = tm / (float)BB;
            out[2] = ti / (float)BB;
            out[3] = td / (float)BB;
            out[4] = tc;
            out[5] = tp / fmaxf(tc, 1.f);
            out[6] = tn / fmaxf(tot_neg, 1.f);
            out[7] = tmi / fmaxf(tc, 1.f);
            g_done = 0;   // reset for next graph replay (deterministic)
        }
    }
}

// ---------------- launch -----------------------------------------------------
extern "C" void kernel_launch(void* const* d_in, const int* in_sizes, int n_in,
                              void* d_out, int out_size) {
    const float*         ps  = (const float*)d_in[0];          // (B,N,C)
    const float*         pbx = (const float*)d_in[1];          // (B,N,4)
    const float*         ap  = (const float*)d_in[2];          // (N,2)
    const float*         st  = (const float*)d_in[3];          // (N,1)
    const float*         bd  = (const float*)d_in[4];          // (B,N,64)
    const float*         gtb = (const float*)d_in[5];          // (B,M,4)
    const int*           gtl = (const int*)d_in[6];            // (B,M)
    const unsigned char* cm  = (const unsigned char*)d_in[7];  // (B,C) bool (dtype detected)
    float*               out = (float*)d_out;                  // 8 scalars

    dim3 ga(MM, BB);
    k_thr<<<ga, 256>>>(ps, pbx, ap, gtl, gtb, cm);
    dim3 gb(NB1, BB);
    k_main<<<gb, T1>>>(ps, pbx, ap, st, gtl, gtb, bd, cm, out);
}

// round 6
// speedup vs baseline: 1.2140x; 1.2140x over previous
#include <cuda_runtime.h>
#include <cuda_bf16.h>
#include <math.h>

// Problem constants (fixed by setup_inputs)
#define BB 16
#define NN 8400
#define CC 80
#define MM 64
#define RR 16
#define KTOP 13
#define NEG_INFF (-1e30f)

static constexpr int T1    = 128;                     // anchors per main block
static constexpr int NB1   = (NN + T1 - 1) / T1;      // 66
static constexpr int NBTOT = NB1 * BB;                // 1056
static constexpr int CAP   = 512;                     // max candidates per GT (<=395 actual)

// ---------------- scratch (static device globals; no allocations) ----------
__device__ unsigned long long g_thr[BB * MM];
__device__ float              g_p2[BB * NB1 * 8];
__device__ unsigned int       g_done = 0;             // reset by last block each run

// ---------------- bit-exact helpers shared by K_A and K_B --------------------
// No FMA contraction allowed here: K_A and K_B must produce identical bits.
__device__ __forceinline__ float iou_sel(float4 a, float4 b) {
    float x1 = fmaxf(a.x, b.x), y1 = fmaxf(a.y, b.y);
    float x2 = fminf(a.z, b.z), y2 = fminf(a.w, b.w);
    float iw = fmaxf(__fsub_rn(x2, x1), 0.f);
    float ih = fmaxf(__fsub_rn(y2, y1), 0.f);
    float inter = __fmul_rn(iw, ih);
    float a1 = __fmul_rn(__fsub_rn(a.z, a.x), __fsub_rn(a.w, a.y));
    float a2 = __fmul_rn(__fsub_rn(b.z, b.x), __fsub_rn(b.w, b.y));
    float den = __fadd_rn(__fsub_rn(__fadd_rn(a1, a2), inter), 1e-7f);
    return __fdiv_rn(inter, den);
}

__device__ __forceinline__ float sigmoid_sel(float x) {   // accurate; selection path
    return __fdiv_rn(1.f, __fadd_rn(1.f, expf(-x)));
}

__device__ __forceinline__ float align_sel(float cls, float iou) {
    float i2 = __fmul_rn(iou, iou);
    float i4 = __fmul_rn(i2, i2);
    float i6 = __fmul_rn(i4, i2);
    return __fmul_rn(cls, i6);                              // alpha=1, beta=6
}

// Sortable key matching jax.lax.top_k semantics: value desc, index asc on ties.
__device__ __forceinline__ unsigned long long pack_key(float v, int n) {
    unsigned int u = __float_as_uint(v);
    u = (u & 0x80000000u) ? ~u : (u | 0x80000000u);
    return ((unsigned long long)u << 32) | (unsigned int)(0xFFFFFFFFu - (unsigned int)n);
}

// class_mask may arrive as uint8 or widened (int32/float32) bools.
// uint8 ones -> bytes 01 01 01 01 (cm[1]!=0); int32/float32 ones -> cm[1]==0.
__device__ __forceinline__ bool mask_at(const unsigned char* cm, bool wide, int idx) {
    return wide ? (((const unsigned int*)cm)[idx] != 0u) : (cm[idx] != 0);
}

// ---------------- K_A: per (b,m) candidate scan -> 13th-largest key ----------
__global__ void __launch_bounds__(256)
k_thr(const float* __restrict__ ps, const float* __restrict__ pb,
      const float* __restrict__ ap, const int* __restrict__ gtl,
      const float* __restrict__ gtb, const unsigned char* __restrict__ cm) {
    const int m = blockIdx.x, b = blockIdx.y;
    const int tid = threadIdx.x;

    __shared__ float4 sbox;
    __shared__ int    slc, svalid, scnt;
    __shared__ unsigned long long skeys[CAP];
    __shared__ unsigned long long sthr;

    if (tid == 0) {
        const float* g = gtb + (b * MM + m) * 4;
        sbox = make_float4(g[0], g[1], g[2], g[3]);
        int l  = gtl[b * MM + m];
        int lc = min(max(l, 0), CC - 1);
        slc = lc;
        const bool wide = (cm[1] == 0);
        svalid = (l >= 0 && l < CC && mask_at(cm, wide, b * CC + lc)) ? 1 : 0;
        scnt = 0;
        sthr = 0ull;
    }
    __syncthreads();

    if (svalid) {
        const float4 box = sbox;
        const int lc = slc;
        for (int n = tid; n < NN; n += 256) {
            float2 a = __ldg((const float2*)ap + n);
            if (a.x >= box.x && a.x <= box.z && a.y >= box.y && a.y <= box.w) {
                float4 pbox = __ldg((const float4*)(pb + ((size_t)b * NN + n) * 4));
                float cls = sigmoid_sel(__ldg(ps + ((size_t)b * NN + n) * CC + lc));
                float al  = align_sel(cls, iou_sel(pbox, box));
                int slot = atomicAdd(&scnt, 1);
                if (slot < CAP) skeys[slot] = pack_key(al, n);
            }
        }
    }
    __syncthreads();

    const int c = min(scnt, CAP);
    if (c >= KTOP) {
        // rank selection: the key with exactly KTOP-1 larger keys is the threshold
        for (int i = tid; i < c; i += 256) {
            unsigned long long k = skeys[i];
            int r = 0;
            for (int j = 0; j < c; j++) r += (skeys[j] > k);
            if (r == KTOP - 1) sthr = k;   // unique (keys distinct by index)
        }
    }
    __syncthreads();
    if (tid == 0) g_thr[b * MM + m] = sthr;
}

// ---------------- K_B: fused per-anchor assignment + loss + finalize ---------
__global__ void __launch_bounds__(T1, 8)
k_main(const float* __restrict__ ps, const float* __restrict__ pb,
       const float* __restrict__ ap, const float* __restrict__ st,
       const int* __restrict__ gtl, const float* __restrict__ gtb,
       const float* __restrict__ bd, const unsigned char* __restrict__ cm,
       float* __restrict__ out) {
    const int b    = blockIdx.y;
    const int tile = blockIdx.x * T1;
    const int tid  = threadIdx.x;
    const int warp = tid >> 5, lane = tid & 31;
    const bool wide = (cm[1] == 0);

    __shared__ float4 sgtb[MM];
    __shared__ int    slab[MM];
    __shared__ unsigned char svalm[MM];
    __shared__ unsigned long long sthr[MM];
    __shared__ float  svc[CC];
    __shared__ float  spart[4 * 8];
    __shared__ float  sbb[4 * 4];       // per-warp minx,maxx,miny,maxy
    __shared__ int    s_mlist[MM];
    __shared__ int    s_mcnt;
    __shared__ unsigned int s_last;

    if (tid < MM) {
        sgtb[tid] = __ldg((const float4*)gtb + b * MM + tid);
        int l  = __ldg(gtl + b * MM + tid);
        int lc = min(max(l, 0), CC - 1);
        slab[tid] = lc;
        svalm[tid] = (l >= 0 && l < CC && mask_at(cm, wide, b * CC + lc)) ? 1 : 0;
        sthr[tid] = g_thr[b * MM + tid];
    }
    if (tid < CC) svc[tid] = mask_at(cm, wide, b * CC + tid) ? 1.f : 0.f;

    const int rows = min(T1, NN - tile);
    const int n = tile + tid;
    float ax = 0.f, ay = 0.f;
    float4 pbox = make_float4(0.f, 0.f, 0.f, 0.f);
    if (tid < rows) {
        float2 a = __ldg((const float2*)ap + n);
        ax = a.x; ay = a.y;
        pbox = __ldg((const float4*)(pb + ((size_t)b * NN + n) * 4));
    }

    // ---- tile anchor bbox (for GT pruning) ----------------------------------
    {
        float mnx = (tid < rows) ? ax :  3.4e38f;
        float mxx = (tid < rows) ? ax : -3.4e38f;
        float mny = (tid < rows) ? ay :  3.4e38f;
        float mxy = (tid < rows) ? ay : -3.4e38f;
#pragma unroll
        for (int off = 16; off > 0; off >>= 1) {
            mnx = fminf(mnx, __shfl_down_sync(0xFFFFFFFFu, mnx, off));
            mxx = fmaxf(mxx, __shfl_down_sync(0xFFFFFFFFu, mxx, off));
            mny = fminf(mny, __shfl_down_sync(0xFFFFFFFFu, mny, off));
            mxy = fmaxf(mxy, __shfl_down_sync(0xFFFFFFFFu, mxy, off));
        }
        if (lane == 0) {
            sbb[warp * 4 + 0] = mnx; sbb[warp * 4 + 1] = mxx;
            sbb[warp * 4 + 2] = mny; sbb[warp * 4 + 3] = mxy;
        }
    }
    __syncthreads();

    if (tid == 0) {
        float mnx = fminf(fminf(sbb[0], sbb[4]),  fminf(sbb[8],  sbb[12]));
        float mxx = fmaxf(fmaxf(sbb[1], sbb[5]),  fmaxf(sbb[9],  sbb[13]));
        float mny = fminf(fminf(sbb[2], sbb[6]),  fminf(sbb[10], sbb[14]));
        float mxy = fmaxf(fmaxf(sbb[3], sbb[7]),  fmaxf(sbb[11], sbb[15]));
        int c = 0;
        for (int m = 0; m < MM; m++) {
            float4 g = sgtb[m];
            if (svalm[m] && g.x <= mxx && g.z >= mnx && g.y <= mxy && g.w >= mny)
                s_mlist[c++] = m;        // ascending m -> first-m argmax preserved
        }
        s_mcnt = c;
    }
    __syncthreads();

    float cnt = 0.f, cis = 0.f, dfs = 0.f, cor = 0.f, pos = 0.f, neg = 0.f, mio = 0.f, sp = 0.f;

    if (tid < rows) {
        const float* myrow = ps + ((size_t)b * NN + n) * CC;
        const float4* myq  = (const float4*)myrow;

        // ---- softplus sum + valid-class max (value-only: fast intrinsics) ----
        // branch-free: multiply by svc; mxl via select.
        float sp0 = 0.f, sp1 = 0.f;
        float mxl = -3.4e38f, anyv = 0.f;
#pragma unroll
        for (int c4 = 0; c4 < 20; c4 += 2) {
            float4 qa = __ldg(myq + c4);
            float4 qb = __ldg(myq + c4 + 1);
            const float* va = &svc[c4 * 4];
            float s;
            s = qa.x; sp0 += va[0] * (fmaxf(s, 0.f) + __logf(1.f + __expf(-fabsf(s)))); mxl = fmaxf(mxl, va[0] != 0.f ? s : -3.4e38f); anyv = fmaxf(anyv, va[0]);
            s = qa.y; sp1 += va[1] * (fmaxf(s, 0.f) + __logf(1.f + __expf(-fabsf(s)))); mxl = fmaxf(mxl, va[1] != 0.f ? s : -3.4e38f); anyv = fmaxf(anyv, va[1]);
            s = qa.z; sp0 += va[2] * (fmaxf(s, 0.f) + __logf(1.f + __expf(-fabsf(s)))); mxl = fmaxf(mxl, va[2] != 0.f ? s : -3.4e38f); anyv = fmaxf(anyv, va[2]);
            s = qa.w; sp1 += va[3] * (fmaxf(s, 0.f) + __logf(1.f + __expf(-fabsf(s)))); mxl = fmaxf(mxl, va[3] != 0.f ? s : -3.4e38f); anyv = fmaxf(anyv, va[3]);
            s = qb.x; sp0 += va[4] * (fmaxf(s, 0.f) + __logf(1.f + __expf(-fabsf(s)))); mxl = fmaxf(mxl, va[4] != 0.f ? s : -3.4e38f); anyv = fmaxf(anyv, va[4]);
            s = qb.y; sp1 += va[5] * (fmaxf(s, 0.f) + __logf(1.f + __expf(-fabsf(s)))); mxl = fmaxf(mxl, va[5] != 0.f ? s : -3.4e38f); anyv = fmaxf(anyv, va[5]);
            s = qb.z; sp0 += va[6] * (fmaxf(s, 0.f) + __logf(1.f + __expf(-fabsf(s)))); mxl = fmaxf(mxl, va[6] != 0.f ? s : -3.4e38f); anyv = fmaxf(anyv, va[6]);
            s = qb.w; sp1 += va[7] * (fmaxf(s, 0.f) + __logf(1.f + __expf(-fabsf(s)))); mxl = fmaxf(mxl, va[7] != 0.f ? s : -3.4e38f); anyv = fmaxf(anyv, va[7]);
        }
        sp = sp0 + sp1;

        // ---- assignment over pruned GT list ---------------------------------
        float best = -3.4e38f; int mg = 0;
        const int mc = s_mcnt;
        for (int mi = 0; mi < mc; mi++) {
            const int m = s_mlist[mi];
            float4 g = sgtb[m];
            if (ax >= g.x && ax <= g.z && ay >= g.y && ay <= g.w) {
                float cls = sigmoid_sel(__ldg(myrow + slab[m]));   // L1-hot
                float al  = align_sel(cls, iou_sel(pbox, g));
                float cand = (pack_key(al, n) >= sthr[m]) ? al : NEG_INFF;
                if (cand > best) { best = cand; mg = m; }   // strict > = first-m argmax
            }
        }
        const bool fg = best > -1.0f;

        if (fg) {
            cnt = 1.f;
            const float4 g = sgtb[mg];
            const int ml = slab[mg];
            const float ov = iou_sel(pbox, g);
            mio = ov;
            float psv = __ldg(myrow + ml);
            pos = 1.f / (1.f + __expf(-psv));
            cor = psv * fmaxf(ov, 0.1f) * svc[ml];

            // CIoU (value-only accuracy)
            float w1 = pbox.z - pbox.x, h1 = pbox.w - pbox.y;
            float w2 = g.z - g.x,       h2 = g.w - g.y;
            float cw = fmaxf(pbox.z, g.z) - fminf(pbox.x, g.x);
            float ch = fmaxf(pbox.w, g.w) - fminf(pbox.y, g.y);
            float c2 = cw * cw + ch * ch + 1e-7f;
            float dx = g.x + g.z - pbox.x - pbox.z;
            float dy = g.y + g.w - pbox.y - pbox.w;
            float rho2 = (dx * dx + dy * dy) * 0.25f;
            float dat = atanf(w2 / (h2 + 1e-7f)) - atanf(w1 / (h1 + 1e-7f));
            float v   = 0.40528473456935108577f * dat * dat;  // 4/pi^2
            float alp = v / (v - ov + 1.0f + 1e-7f);
            cis = 1.f - (ov - (rho2 / c2 + v * alp));

            // DFL
            const float stv = __ldg(st + n);
            float dar[4] = { (ax - g.x) / stv, (ay - g.y) / stv,
                             (g.z - ax) / stv, (g.w - ay) / stv };
            const float* bdp = bd + ((size_t)b * NN + n) * 64;
            const float4* bq = (const float4*)bdp;
#pragma unroll
            for (int sd = 0; sd < 4; sd++) {
                float4 q0 = __ldg(bq + sd * 4 + 0);
                float4 q1 = __ldg(bq + sd * 4 + 1);
                float4 q2 = __ldg(bq + sd * 4 + 2);
                float4 q3 = __ldg(bq + sd * 4 + 3);
                float mv = q0.x;
                mv = fmaxf(mv, q0.y); mv = fmaxf(mv, q0.z); mv = fmaxf(mv, q0.w);
                mv = fmaxf(mv, q1.x); mv = fmaxf(mv, q1.y); mv = fmaxf(mv, q1.z); mv = fmaxf(mv, q1.w);
                mv = fmaxf(mv, q2.x); mv = fmaxf(mv, q2.y); mv = fmaxf(mv, q2.z); mv = fmaxf(mv, q2.w);
                mv = fmaxf(mv, q3.x); mv = fmaxf(mv, q3.y); mv = fmaxf(mv, q3.z); mv = fmaxf(mv, q3.w);
                float se = __expf(q0.x - mv) + __expf(q0.y - mv) + __expf(q0.z - mv) + __expf(q0.w - mv)
                         + __expf(q1.x - mv) + __expf(q1.y - mv) + __expf(q1.z - mv) + __expf(q1.w - mv)
                         + __expf(q2.x - mv) + __expf(q2.y - mv) + __expf(q2.z - mv) + __expf(q2.w - mv)
                         + __expf(q3.x - mv) + __expf(q3.y - mv) + __expf(q3.z - mv) + __expf(q3.w - mv);
                float lse = mv + __logf(se);
                float d = fminf(fmaxf(dar[sd], 0.f), 14.99f);
                int tl = (int)d;
                int tr = min(tl + 1, RR - 1);
                float wl = (float)tr - d;
                float wr = 1.f - wl;
                float vtl = __ldg(bdp + sd * 16 + tl);
                float vtr = __ldg(bdp + sd * 16 + tr);
                dfs += (lse - vtl) * wl + (lse - vtr) * wr;
            }
        } else {
            neg = (anyv != 0.f) ? (1.f / (1.f + __expf(-mxl))) : NEG_INFF;
        }
    }

    // ---- 8-way block reduction (warp shuffles + one smem stage) -------------
    float v[8] = {cnt, cis, dfs, cor, pos, neg, mio, sp};
#pragma unroll
    for (int k = 0; k < 8; k++) {
#pragma unroll
        for (int off = 16; off > 0; off >>= 1)
            v[k] += __shfl_down_sync(0xFFFFFFFFu, v[k], off);
    }
    if (lane == 0) {
#pragma unroll
        for (int k = 0; k < 8; k++) spart[warp * 8 + k] = v[k];
    }
    __syncthreads();
    if (tid == 0) {
        float* o = &g_p2[((size_t)b * NB1 + blockIdx.x) * 8];
#pragma unroll
        for (int k = 0; k < 8; k++)
            o[k] = spart[k] + spart[8 + k] + spart[16 + k] + spart[24 + k];
        __threadfence();
        unsigned int d = atomicAdd(&g_done, 1u);
        s_last = (d == NBTOT - 1) ? 1u : 0u;
    }
    __syncthreads();

    // ---- last block: finalize ----------------------------------------------
    if (s_last) {
        __shared__ float s_match[BB], s_iou[BB], s_dfl[BB], s_cnt[BB], s_pos[BB], s_neg[BB], s_mio[BB];
        // 4 warps, each handles 4 batch samples
        for (int bsel = warp; bsel < BB; bsel += 4) {
            float w[8] = {0.f, 0.f, 0.f, 0.f, 0.f, 0.f, 0.f, 0.f};
            for (int i = lane; i < NB1; i += 32) {
                const float* p = &g_p2[((size_t)bsel * NB1 + i) * 8];
#pragma unroll
                for (int k = 0; k < 8; k++) w[k] += p[k];
            }
            float vcs = 0.f;
            for (int c = lane; c < CC; c += 32)
                vcs += mask_at(cm, wide, bsel * CC + c) ? 1.f : 0.f;
#pragma unroll
            for (int off = 16; off > 0; off >>= 1) {
#pragma unroll
                for (int k = 0; k < 8; k++) w[k] += __shfl_down_sync(0xFFFFFFFFu, w[k], off);
                vcs += __shfl_down_sync(0xFFFFFFFFu, vcs, off);
            }
            if (lane == 0) {
                float cb = w[0];
                s_match[bsel] = (w[7] - w[3]) / ((float)NN * fmaxf(vcs, 1.f));
                s_iou[bsel]   = (cb > 0.f) ? w[1] / fmaxf(cb, 1.f) : 0.f;
                s_dfl[bsel]   = (cb > 0.f) ? w[2] / fmaxf(cb * 4.f, 1.f) : 0.f;
                s_cnt[bsel] = cb; s_pos[bsel] = w[4]; s_neg[bsel] = w[5]; s_mio[bsel] = w[6];
            }
        }
        __syncthreads();
        if (tid == 0) {
            float tm = 0.f, ti = 0.f, td = 0.f, tc = 0.f, tp = 0.f, tn = 0.f, tmi = 0.f;
            for (int i = 0; i < BB; i++) {
                tm += s_match[i]; ti += s_iou[i]; td += s_dfl[i];
                tc += s_cnt[i];  tp += s_pos[i]; tn += s_neg[i]; tmi += s_mio[i];
            }
            float tot_neg = (float)BB * (float)NN - tc;
            out[0] = (0.5f * tm + 7.5f * ti + 1.5f * td) / (float)BB;
            out[1] = tm / (float)BB;
            out[2] = ti / (float)BB;
            out[3] = td / (float)BB;
            out[4] = tc;
            out[5] = tp / fmaxf(tc, 1.f);
            out[6] = tn / fmaxf(tot_neg, 1.f);
            out[7] = tmi / fmaxf(tc, 1.f);
            g_done = 0;   // reset for next graph replay (deterministic)
        }
    }
}

// ---------------- launch -----------------------------------------------------
extern "C" void kernel_launch(void* const* d_in, const int* in_sizes, int n_in,
                              void* d_out, int out_size) {
    const float*         ps  = (const float*)d_in[0];          // (B,N,C)
    const float*         pbx = (const float*)d_in[1];          // (B,N,4)
    const float*         ap  = (const float*)d_in[2];          // (N,2)
    const float*         st  = (const float*)d_in[3];          // (N,1)
    const float*         bd  = (const float*)d_in[4];          // (B,N,64)
    const float*         gtb = (const float*)d_in[5];          // (B,M,4)
    const int*           gtl = (const int*)d_in[6];            // (B,M)
    const unsigned char* cm  = (const unsigned char*)d_in[7];  // (B,C) bool (dtype detected)
    float*               out = (float*)d_out;                  // 8 scalars

    dim3 ga(MM, BB);
    k_thr<<<ga, 256>>>(ps, pbx, ap, gtl, gtb, cm);
    dim3 gb(NB1, BB);
    k_main<<<gb, T1>>>(ps, pbx, ap, st, gtl, gtb, bd, cm, out);
}